// round 1
// baseline (speedup 1.0000x reference)
#include <cuda_runtime.h>
#include <math.h>

#define HF 128
#define WF 128
#define DF 512
#define NA 65536
#define MAXDET 512
#define HIDDEN 1024
#define PDIM (9*512)   // 3*3*512 = 4608

typedef unsigned long long u64;
typedef unsigned int u32;

// ---------------- device scratch (static, no allocation) ----------------
__device__ __align__(16) u64   g_keysA[NA];
__device__ __align__(16) u64   g_keysB[NA/2];
__device__ __align__(16) float g_sel[MAXDET*4];
__device__ float g_scores[MAXDET];
__device__ int   g_valid[MAXDET];
__device__ u64   g_mask[MAXDET*8];
__device__ int   g_keep[MAXDET];
__device__ __align__(16) float g_pooled[MAXDET*PDIM];
__device__ __align__(16) float g_h1[MAXDET*HIDDEN];
__device__ __align__(16) float g_h2[MAXDET*HIDDEN];

// ---------------- 1) scores + sort keys ----------------
// anchor n -> i = n/512, j = (n/4)%128, k = n%4
// obj pair at rpn_obj[(i*128+j)*8 + 2k .. 2k+1]
__global__ void score_kernel(const float* __restrict__ obj, u64* __restrict__ keys) {
    int n = blockIdx.x * 256 + threadIdx.x;
    int cell = n >> 2;
    int k = n & 3;
    float o0 = obj[cell*8 + 2*k];
    float o1 = obj[cell*8 + 2*k + 1];
    float m  = fmaxf(o0, o1);
    float e0 = expf(o0 - m);
    float e1 = expf(o1 - m);
    float s  = e1 / (e0 + e1);
    u32 bits = (s > 0.5f) ? __float_as_uint(s) : __float_as_uint(-INFINITY);
    // monotonic (ascending) transform of float bits
    u32 mono = (bits & 0x80000000u) ? ~bits : (bits | 0x80000000u);
    keys[n] = ((u64)mono << 32) | (u32)(~n);   // tie-break: lower index wins
}

// ---------------- 2) top-512 selection: bitonic tournament ----------------
__global__ void __launch_bounds__(1024) sort1024_kernel(const u64* __restrict__ src,
                                                        u64* __restrict__ dst) {
    __shared__ u64 s[1024];
    int tid = threadIdx.x;
    s[tid] = src[blockIdx.x * 1024 + tid];
    __syncthreads();
    for (int k = 2; k <= 1024; k <<= 1) {
        for (int j = k >> 1; j > 0; j >>= 1) {
            int ixj = tid ^ j;
            if (ixj > tid) {
                u64 a = s[tid], b = s[ixj];
                bool desc = ((tid & k) == 0);
                if (desc ? (a < b) : (a > b)) { s[tid] = b; s[ixj] = a; }
            }
            __syncthreads();
        }
    }
    if (tid < 512) dst[blockIdx.x * 512 + tid] = s[tid];   // top-512 of this chunk
}

// merge two descending 512-chunks, keep top 512 (descending)
__global__ void __launch_bounds__(1024) merge_kernel(const u64* __restrict__ src,
                                                     u64* __restrict__ dst) {
    __shared__ u64 s[1024];
    int tid = threadIdx.x;
    int p = blockIdx.x;
    // chunk 2p descending + chunk 2p+1 reversed (ascending) => bitonic
    s[tid] = (tid < 512) ? src[p*1024 + tid]
                         : src[p*1024 + 512 + (1023 - tid)];
    __syncthreads();
    for (int j = 512; j > 0; j >>= 1) {
        int ixj = tid ^ j;
        if (ixj > tid) {
            u64 a = s[tid], b = s[ixj];
            if (a < b) { s[tid] = b; s[ixj] = a; }
        }
        __syncthreads();
    }
    if (tid < 512) dst[p*512 + tid] = s[tid];
}

// ---------------- 3) gather boxes/scores for top-512 ----------------
__global__ void gather_kernel(const float* __restrict__ reg,
                              const u64* __restrict__ keys) {
    int t = threadIdx.x;
    u64 key = keys[t];
    u32 lo = (u32)key;
    u32 hi = (u32)(key >> 32);
    u32 n  = ~lo;
    u32 fb = (hi & 0x80000000u) ? (hi ^ 0x80000000u) : ~hi;
    float score = __uint_as_float(fb);
    int k = n & 3;
    int j = (n >> 2) & 127;
    int i = n >> 9;
    float sz = (float)((k + 1) * 32);
    int base = ((i*128 + j) * 16) + k*4;
    float r0 = reg[base+0], r1 = reg[base+1], r2 = reg[base+2], r3 = reg[base+3];
    float acx = j * 16.0f + 8.0f;
    float acy = i * 16.0f + 8.0f;
    float cx = acx + r0 * sz;
    float cy = acy + r1 * sz;
    float w  = sz * expf(r2);
    float h  = sz * expf(r3);
    g_sel[t*4+0] = cx - w * 0.5f;
    g_sel[t*4+1] = cy - h * 0.5f;
    g_sel[t*4+2] = w;
    g_sel[t*4+3] = h;
    bool valid = (score > 0.5f);
    g_scores[t] = valid ? score : 0.0f;
    g_valid[t]  = valid ? 1 : 0;
}

// ---------------- 4) IoU bitmask matrix ----------------
__global__ void iou_kernel() {
    __shared__ float4 bx[512];
    __shared__ u32 warpbits[16];
    int i = blockIdx.x;
    int j = threadIdx.x;
    bx[j] = ((const float4*)g_sel)[j];
    __syncthreads();
    float4 a = bx[i], b = bx[j];
    float ax2 = a.x + a.z, ay2 = a.y + a.w;
    float bx2 = b.x + b.z, by2 = b.y + b.w;
    float ix = fmaxf(0.0f, fminf(ax2, bx2) - fmaxf(a.x, b.x));
    float iy = fmaxf(0.0f, fminf(ay2, by2) - fmaxf(a.y, b.y));
    float inter = ix * iy;
    float iou = inter / (a.z*a.w + b.z*b.w - inter + 1e-8f);
    u32 ball = __ballot_sync(0xffffffffu, iou > 0.3f);
    if ((j & 31) == 0) warpbits[j >> 5] = ball;
    __syncthreads();
    if (j < 8)
        g_mask[i*8 + j] = ((u64)warpbits[2*j+1] << 32) | (u64)warpbits[2*j];
}

// ---------------- 5) greedy NMS scan (matches reference scan) ----------------
__global__ void nms_kernel() {
    __shared__ u64 m[MAXDET*8];
    __shared__ int sval[MAXDET];
    for (int idx = threadIdx.x; idx < MAXDET*8; idx += blockDim.x) m[idx] = g_mask[idx];
    for (int idx = threadIdx.x; idx < MAXDET;   idx += blockDim.x) sval[idx] = g_valid[idx];
    __syncthreads();
    if (threadIdx.x == 0) {
        u64 removed[8] = {0,0,0,0,0,0,0,0};
        for (int i = 0; i < MAXDET; i++) {
            int w = i >> 6, bit = i & 63;
            int k = sval[i] && !((removed[w] >> bit) & 1ULL);
            g_keep[i] = k;
            if (k) {
                #pragma unroll
                for (int q = 0; q < 8; q++) removed[q] |= m[i*8 + q];
            }
        }
    }
}

// ---------------- 6) ROI align (block per box, thread per channel) ----------------
__global__ void __launch_bounds__(512) roi_kernel(const float* __restrict__ feat) {
    int mrow = blockIdx.x;
    __shared__ float bxs[4];
    __shared__ int   xs0[6], xs1[6], ys0[6], ys1[6];
    __shared__ float wxs[6], wys[6];
    int tid = threadIdx.x;
    if (tid < 4) bxs[tid] = g_sel[mrow*4 + tid];
    __syncthreads();
    if (tid < 6) {
        float t = (tid + 0.5f) / 6.0f;
        float fx = (bxs[0] + t * bxs[2]) / 16.0f - 0.5f;
        float fy = (bxs[1] + t * bxs[3]) / 16.0f - 0.5f;
        fx = fminf(fmaxf(fx, 0.0f), 127.0f);
        fy = fminf(fmaxf(fy, 0.0f), 127.0f);
        int x0 = (int)floorf(fx);
        int y0 = (int)floorf(fy);
        xs0[tid] = x0; xs1[tid] = min(x0 + 1, 127); wxs[tid] = fx - (float)x0;
        ys0[tid] = y0; ys1[tid] = min(y0 + 1, 127); wys[tid] = fy - (float)y0;
    }
    __syncthreads();
    int c = tid;   // 512 threads = 512 channels
    float mx[9];
    #pragma unroll
    for (int p = 0; p < 9; p++) mx[p] = -INFINITY;
    #pragma unroll
    for (int ty = 0; ty < 6; ty++) {
        int y0 = ys0[ty], y1 = ys1[ty];
        float wy = wys[ty], wy0 = 1.0f - wy;
        #pragma unroll
        for (int tx = 0; tx < 6; tx++) {
            int x0 = xs0[tx], x1 = xs1[tx];
            float wx = wxs[tx], wx0 = 1.0f - wx;
            float f00 = feat[(y0*128 + x0)*512 + c];
            float f01 = feat[(y0*128 + x1)*512 + c];
            float f10 = feat[(y1*128 + x0)*512 + c];
            float f11 = feat[(y1*128 + x1)*512 + c];
            float v = f00*wy0*wx0 + f01*wy0*wx + f10*wy*wx0 + f11*wy*wx;
            int p = (ty >> 1)*3 + (tx >> 1);
            mx[p] = fmaxf(mx[p], v);
        }
    }
    #pragma unroll
    for (int p = 0; p < 9; p++)
        g_pooled[mrow*PDIM + p*512 + c] = mx[p];
}

// ---------------- 7) fused FC GEMM: C = relu?(A @ W + b) ----------------
// A: [512, K] row-major, W: [K, N] row-major, C: [512, N].
// BM=BN=64, BK=16, 256 threads, 4x4 per thread.
__global__ void __launch_bounds__(256) fc_kernel(const float* __restrict__ A,
                                                 const float* __restrict__ W,
                                                 const float* __restrict__ bias,
                                                 float* __restrict__ C,
                                                 int K, int N, int do_relu) {
    __shared__ float As[16][64];
    __shared__ float Bs[16][64];
    int tid = threadIdx.x;
    int br = blockIdx.y * 64;
    int bc = blockIdx.x * 64;
    int ty = tid >> 4;          // 0..15 -> row group
    int tx = tid & 15;          // 0..15 -> col group
    int arow = tid >> 2;        // 0..63
    int akq  = (tid & 3) << 2;  // 0,4,8,12
    int bkr  = tid >> 4;        // 0..15
    int bcq  = (tid & 15) << 2; // 0..60
    float acc[4][4];
    #pragma unroll
    for (int i = 0; i < 4; i++)
        #pragma unroll
        for (int j = 0; j < 4; j++) acc[i][j] = 0.0f;

    for (int k0 = 0; k0 < K; k0 += 16) {
        float4 av = *(const float4*)&A[(br + arow)*K + k0 + akq];
        As[akq+0][arow] = av.x;
        As[akq+1][arow] = av.y;
        As[akq+2][arow] = av.z;
        As[akq+3][arow] = av.w;
        float4 bv = *(const float4*)&W[(u64)(k0 + bkr)*N + bc + bcq];
        *(float4*)&Bs[bkr][bcq] = bv;
        __syncthreads();
        #pragma unroll
        for (int kk = 0; kk < 16; kk++) {
            float4 a4 = *(const float4*)&As[kk][ty << 2];
            float4 b4 = *(const float4*)&Bs[kk][tx << 2];
            float a[4] = {a4.x, a4.y, a4.z, a4.w};
            float b[4] = {b4.x, b4.y, b4.z, b4.w};
            #pragma unroll
            for (int i = 0; i < 4; i++)
                #pragma unroll
                for (int j = 0; j < 4; j++)
                    acc[i][j] = fmaf(a[i], b[j], acc[i][j]);
        }
        __syncthreads();
    }
    #pragma unroll
    for (int i = 0; i < 4; i++) {
        #pragma unroll
        for (int j = 0; j < 4; j++) {
            int col = bc + (tx << 2) + j;
            float v = acc[i][j] + bias[col];
            if (do_relu) v = fmaxf(v, 0.0f);
            C[(u64)(br + (ty << 2) + i)*N + col] = v;
        }
    }
}

// ---------------- 8) FC3 + unparameterize + gate by keep ----------------
__global__ void fc3_final_kernel(const float* __restrict__ W3,
                                 const float* __restrict__ b3,
                                 float* __restrict__ out) {
    int mrow = blockIdx.x;
    int tid = threadIdx.x;     // 128
    float acc[4] = {0,0,0,0};
    for (int k = tid; k < HIDDEN; k += 128) {
        float hv = g_h2[mrow*HIDDEN + k];
        #pragma unroll
        for (int c = 0; c < 4; c++) acc[c] = fmaf(hv, W3[k*4 + c], acc[c]);
    }
    __shared__ float red[4][128];
    #pragma unroll
    for (int c = 0; c < 4; c++) red[c][tid] = acc[c];
    __syncthreads();
    for (int s = 64; s > 0; s >>= 1) {
        if (tid < s) {
            #pragma unroll
            for (int c = 0; c < 4; c++) red[c][tid] += red[c][tid + s];
        }
        __syncthreads();
    }
    if (tid == 0) {
        if (!g_keep[mrow]) {
            #pragma unroll
            for (int c = 0; c < 5; c++) out[mrow*5 + c] = 0.0f;
        } else {
            float d0 = red[0][0] + b3[0];
            float d1 = red[1][0] + b3[1];
            float d2 = red[2][0] + b3[2];
            float d3 = red[3][0] + b3[3];
            float sx = g_sel[mrow*4+0], sy = g_sel[mrow*4+1];
            float sw = g_sel[mrow*4+2], sh = g_sel[mrow*4+3];
            float acx = sx + sw * 0.5f;
            float acy = sy + sh * 0.5f;
            float cx = acx + d0 * sw;
            float cy = acy + d1 * sh;
            float w  = sw * expf(d2);
            float h  = sh * expf(d3);
            out[mrow*5+0] = cx - w * 0.5f;
            out[mrow*5+1] = cy - h * 0.5f;
            out[mrow*5+2] = w;
            out[mrow*5+3] = h;
            out[mrow*5+4] = g_scores[mrow];
        }
    }
}

// ---------------- launch ----------------
extern "C" void kernel_launch(void* const* d_in, const int* in_sizes, int n_in,
                              void* d_out, int out_size) {
    const float* features = (const float*)d_in[0];
    const float* rpn_obj  = (const float*)d_in[1];
    const float* rpn_reg  = (const float*)d_in[2];
    // d_in[3] anchors: derived analytically, unused
    const float* W1 = (const float*)d_in[4];
    const float* b1 = (const float*)d_in[5];
    const float* W2 = (const float*)d_in[6];
    const float* b2 = (const float*)d_in[7];
    const float* W3 = (const float*)d_in[8];
    const float* b3 = (const float*)d_in[9];
    float* out = (float*)d_out;

    u64 *kA, *kB; float *pooled, *h1, *h2;
    cudaGetSymbolAddress((void**)&kA, g_keysA);
    cudaGetSymbolAddress((void**)&kB, g_keysB);
    cudaGetSymbolAddress((void**)&pooled, g_pooled);
    cudaGetSymbolAddress((void**)&h1, g_h1);
    cudaGetSymbolAddress((void**)&h2, g_h2);

    score_kernel<<<NA/256, 256>>>(rpn_obj, kA);

    sort1024_kernel<<<64, 1024>>>(kA, kB);   // 64 chunks of 512 in kB
    merge_kernel<<<32, 1024>>>(kB, kA);      // 32 chunks
    merge_kernel<<<16, 1024>>>(kA, kB);      // 16
    merge_kernel<<<8,  1024>>>(kB, kA);      // 8
    merge_kernel<<<4,  1024>>>(kA, kB);      // 4
    merge_kernel<<<2,  1024>>>(kB, kA);      // 2
    merge_kernel<<<1,  1024>>>(kA, kB);      // final top-512 in kB

    gather_kernel<<<1, 512>>>(rpn_reg, kB);
    iou_kernel<<<512, 512>>>();
    nms_kernel<<<1, 256>>>();
    roi_kernel<<<512, 512>>>(features);

    dim3 g1(HIDDEN/64, MAXDET/64);   // 16 x 8
    fc_kernel<<<g1, 256>>>(pooled, W1, b1, h1, PDIM,   HIDDEN, 1);
    fc_kernel<<<g1, 256>>>(h1,     W2, b2, h2, HIDDEN, HIDDEN, 1);
    fc3_final_kernel<<<MAXDET, 128>>>(W3, b3, out);
}

// round 3
// speedup vs baseline: 1.3735x; 1.3735x over previous
#include <cuda_runtime.h>
#include <cuda_bf16.h>
#include <math.h>

#define HF 128
#define WF 128
#define DF 512
#define NA 65536
#define MAXDET 512
#define HIDDEN 1024
#define PDIM (9*512)   // 4608

typedef unsigned long long u64;
typedef unsigned int u32;

// ---------------- device scratch (static, no allocation) ----------------
__device__ __align__(16) u64   g_keysA[NA];
__device__ __align__(16) u64   g_keysB[NA/2];
__device__ __align__(16) float g_sel[MAXDET*4];
__device__ float g_scores[MAXDET];
__device__ int   g_valid[MAXDET];
__device__ u64   g_mask[MAXDET*8];
__device__ int   g_keep[MAXDET];

// bf16 hi/lo split activations & weights
__device__ __align__(16) __nv_bfloat16 g_Ahi[MAXDET*PDIM];
__device__ __align__(16) __nv_bfloat16 g_Alo[MAXDET*PDIM];
__device__ __align__(16) __nv_bfloat16 g_W1Th[HIDDEN*PDIM];
__device__ __align__(16) __nv_bfloat16 g_W1Tl[HIDDEN*PDIM];
__device__ __align__(16) __nv_bfloat16 g_W2Th[HIDDEN*HIDDEN];
__device__ __align__(16) __nv_bfloat16 g_W2Tl[HIDDEN*HIDDEN];
__device__ __align__(16) __nv_bfloat16 g_h1hi[MAXDET*HIDDEN];
__device__ __align__(16) __nv_bfloat16 g_h1lo[MAXDET*HIDDEN];
__device__ __align__(16) __nv_bfloat16 g_h2hi[MAXDET*HIDDEN];
__device__ __align__(16) __nv_bfloat16 g_h2lo[MAXDET*HIDDEN];

// ---------------- low-level helpers (plain sm_103-legal PTX only) ----------------
__device__ __forceinline__ u32 smem_u32(const void* p) {
    u32 a;
    asm("{ .reg .u64 t; cvta.to.shared.u64 t, %1; cvt.u32.u64 %0, t; }" : "=r"(a) : "l"(p));
    return a;
}
#define CPA16(dst, src) \
    asm volatile("cp.async.cg.shared.global [%0], [%1], 16;" :: "r"(dst), "l"(src) : "memory")
#define CPA_COMMIT() asm volatile("cp.async.commit_group;" ::: "memory")
#define CPA_WAIT0()  asm volatile("cp.async.wait_group 0;" ::: "memory")

__device__ __forceinline__ void ldsm4(u32* r, u32 addr) {
    asm volatile("ldmatrix.sync.aligned.m8n8.x4.shared.b16 {%0,%1,%2,%3}, [%4];"
                 : "=r"(r[0]), "=r"(r[1]), "=r"(r[2]), "=r"(r[3]) : "r"(addr));
}
__device__ __forceinline__ void ldsm2(u32* r, u32 addr) {
    asm volatile("ldmatrix.sync.aligned.m8n8.x2.shared.b16 {%0,%1}, [%2];"
                 : "=r"(r[0]), "=r"(r[1]) : "r"(addr));
}
__device__ __forceinline__ void mma16816(float* d, const u32* a, const u32* b) {
    asm volatile("mma.sync.aligned.m16n8k16.row.col.f32.bf16.bf16.f32 "
                 "{%0,%1,%2,%3}, {%4,%5,%6,%7}, {%8,%9}, {%0,%1,%2,%3};"
                 : "+f"(d[0]), "+f"(d[1]), "+f"(d[2]), "+f"(d[3])
                 : "r"(a[0]), "r"(a[1]), "r"(a[2]), "r"(a[3]), "r"(b[0]), "r"(b[1]));
}

// ---------------- 1) scores + sort keys ----------------
__global__ void score_kernel(const float* __restrict__ obj, u64* __restrict__ keys) {
    int n = blockIdx.x * 256 + threadIdx.x;
    int cell = n >> 2;
    int k = n & 3;
    float o0 = obj[cell*8 + 2*k];
    float o1 = obj[cell*8 + 2*k + 1];
    float m  = fmaxf(o0, o1);
    float e0 = expf(o0 - m);
    float e1 = expf(o1 - m);
    float s  = e1 / (e0 + e1);
    u32 bits = (s > 0.5f) ? __float_as_uint(s) : __float_as_uint(-INFINITY);
    u32 mono = (bits & 0x80000000u) ? ~bits : (bits | 0x80000000u);
    keys[n] = ((u64)mono << 32) | (u32)(~n);
}

// ---------------- 2) top-512: bitonic tournament ----------------
__global__ void __launch_bounds__(1024) sort1024_kernel(const u64* __restrict__ src,
                                                        u64* __restrict__ dst) {
    __shared__ u64 s[1024];
    int tid = threadIdx.x;
    s[tid] = src[blockIdx.x * 1024 + tid];
    __syncthreads();
    for (int k = 2; k <= 1024; k <<= 1) {
        for (int j = k >> 1; j > 0; j >>= 1) {
            int ixj = tid ^ j;
            if (ixj > tid) {
                u64 a = s[tid], b = s[ixj];
                bool desc = ((tid & k) == 0);
                if (desc ? (a < b) : (a > b)) { s[tid] = b; s[ixj] = a; }
            }
            __syncthreads();
        }
    }
    if (tid < 512) dst[blockIdx.x * 512 + tid] = s[tid];
}

__global__ void __launch_bounds__(1024) merge_kernel(const u64* __restrict__ src,
                                                     u64* __restrict__ dst) {
    __shared__ u64 s[1024];
    int tid = threadIdx.x;
    int p = blockIdx.x;
    s[tid] = (tid < 512) ? src[p*1024 + tid] : src[p*1024 + 512 + (1023 - tid)];
    __syncthreads();
    for (int j = 512; j > 0; j >>= 1) {
        int ixj = tid ^ j;
        if (ixj > tid) {
            u64 a = s[tid], b = s[ixj];
            if (a < b) { s[tid] = b; s[ixj] = a; }
        }
        __syncthreads();
    }
    if (tid < 512) dst[p*512 + tid] = s[tid];
}

// ---------------- 3) gather ----------------
__global__ void gather_kernel(const float* __restrict__ reg,
                              const u64* __restrict__ keys) {
    int t = threadIdx.x;
    u64 key = keys[t];
    u32 lo = (u32)key;
    u32 hi = (u32)(key >> 32);
    u32 n  = ~lo;
    u32 fb = (hi & 0x80000000u) ? (hi ^ 0x80000000u) : ~hi;
    float score = __uint_as_float(fb);
    int k = n & 3;
    int j = (n >> 2) & 127;
    int i = n >> 9;
    float sz = (float)((k + 1) * 32);
    int base = ((i*128 + j) * 16) + k*4;
    float r0 = reg[base+0], r1 = reg[base+1], r2 = reg[base+2], r3 = reg[base+3];
    float acx = j * 16.0f + 8.0f;
    float acy = i * 16.0f + 8.0f;
    float cx = acx + r0 * sz;
    float cy = acy + r1 * sz;
    float w  = sz * expf(r2);
    float h  = sz * expf(r3);
    g_sel[t*4+0] = cx - w * 0.5f;
    g_sel[t*4+1] = cy - h * 0.5f;
    g_sel[t*4+2] = w;
    g_sel[t*4+3] = h;
    bool valid = (score > 0.5f);
    g_scores[t] = valid ? score : 0.0f;
    g_valid[t]  = valid ? 1 : 0;
}

// ---------------- 4) IoU bitmask ----------------
__global__ void iou_kernel() {
    __shared__ float4 bx[512];
    __shared__ u32 warpbits[16];
    int i = blockIdx.x;
    int j = threadIdx.x;
    bx[j] = ((const float4*)g_sel)[j];
    __syncthreads();
    float4 a = bx[i], b = bx[j];
    float ax2 = a.x + a.z, ay2 = a.y + a.w;
    float bx2 = b.x + b.z, by2 = b.y + b.w;
    float ix = fmaxf(0.0f, fminf(ax2, bx2) - fmaxf(a.x, b.x));
    float iy = fmaxf(0.0f, fminf(ay2, by2) - fmaxf(a.y, b.y));
    float inter = ix * iy;
    float iou = inter / (a.z*a.w + b.z*b.w - inter + 1e-8f);
    u32 ball = __ballot_sync(0xffffffffu, iou > 0.3f);
    if ((j & 31) == 0) warpbits[j >> 5] = ball;
    __syncthreads();
    if (j < 8)
        g_mask[i*8 + j] = ((u64)warpbits[2*j+1] << 32) | (u64)warpbits[2*j];
}

// ---------------- 5) NMS scan ----------------
__global__ void nms_kernel() {
    __shared__ u64 m[MAXDET*8];
    __shared__ int sval[MAXDET];
    for (int idx = threadIdx.x; idx < MAXDET*8; idx += blockDim.x) m[idx] = g_mask[idx];
    for (int idx = threadIdx.x; idx < MAXDET;   idx += blockDim.x) sval[idx] = g_valid[idx];
    __syncthreads();
    if (threadIdx.x == 0) {
        u64 removed[8] = {0,0,0,0,0,0,0,0};
        for (int i = 0; i < MAXDET; i++) {
            int w = i >> 6, bit = i & 63;
            int k = sval[i] && !((removed[w] >> bit) & 1ULL);
            g_keep[i] = k;
            if (k) {
                #pragma unroll
                for (int q = 0; q < 8; q++) removed[q] |= m[i*8 + q];
            }
        }
    }
}

// ---------------- 6) ROI align -> bf16 hi/lo ----------------
__global__ void __launch_bounds__(512) roi_kernel(const float* __restrict__ feat) {
    int mrow = blockIdx.x;
    __shared__ float bxs[4];
    __shared__ int   xs0[6], xs1[6], ys0[6], ys1[6];
    __shared__ float wxs[6], wys[6];
    int tid = threadIdx.x;
    if (tid < 4) bxs[tid] = g_sel[mrow*4 + tid];
    __syncthreads();
    if (tid < 6) {
        float t = (tid + 0.5f) / 6.0f;
        float fx = (bxs[0] + t * bxs[2]) / 16.0f - 0.5f;
        float fy = (bxs[1] + t * bxs[3]) / 16.0f - 0.5f;
        fx = fminf(fmaxf(fx, 0.0f), 127.0f);
        fy = fminf(fmaxf(fy, 0.0f), 127.0f);
        int x0 = (int)floorf(fx);
        int y0 = (int)floorf(fy);
        xs0[tid] = x0; xs1[tid] = min(x0 + 1, 127); wxs[tid] = fx - (float)x0;
        ys0[tid] = y0; ys1[tid] = min(y0 + 1, 127); wys[tid] = fy - (float)y0;
    }
    __syncthreads();
    int c = tid;
    float mx[9];
    #pragma unroll
    for (int p = 0; p < 9; p++) mx[p] = -INFINITY;
    #pragma unroll
    for (int ty = 0; ty < 6; ty++) {
        int y0 = ys0[ty], y1 = ys1[ty];
        float wy = wys[ty], wy0 = 1.0f - wy;
        #pragma unroll
        for (int tx = 0; tx < 6; tx++) {
            int x0 = xs0[tx], x1 = xs1[tx];
            float wx = wxs[tx], wx0 = 1.0f - wx;
            float f00 = feat[(y0*128 + x0)*512 + c];
            float f01 = feat[(y0*128 + x1)*512 + c];
            float f10 = feat[(y1*128 + x0)*512 + c];
            float f11 = feat[(y1*128 + x1)*512 + c];
            float v = f00*wy0*wx0 + f01*wy0*wx + f10*wy*wx0 + f11*wy*wx;
            int p = (ty >> 1)*3 + (tx >> 1);
            mx[p] = fmaxf(mx[p], v);
        }
    }
    #pragma unroll
    for (int p = 0; p < 9; p++) {
        float v = mx[p];
        __nv_bfloat16 h = __float2bfloat16(v);
        __nv_bfloat16 l = __float2bfloat16(v - __bfloat162float(h));
        g_Ahi[mrow*PDIM + p*512 + c] = h;
        g_Alo[mrow*PDIM + p*512 + c] = l;
    }
}

// ---------------- 7) weight transpose + hi/lo split ----------------
// W [K][N] fp32 row-major -> T [N][K] bf16 hi/lo
__global__ void tsplit_kernel(const float* __restrict__ W,
                              __nv_bfloat16* __restrict__ Th,
                              __nv_bfloat16* __restrict__ Tl,
                              int K, int N) {
    __shared__ float t[32][33];
    int n0 = blockIdx.x * 32, k0 = blockIdx.y * 32;
    int tx = threadIdx.x, ty = threadIdx.y;   // 32 x 8
    #pragma unroll
    for (int i = 0; i < 4; i++)
        t[ty + 8*i][tx] = W[(size_t)(k0 + ty + 8*i)*N + n0 + tx];
    __syncthreads();
    #pragma unroll
    for (int i = 0; i < 4; i++) {
        float v = t[tx][ty + 8*i];
        __nv_bfloat16 h = __float2bfloat16(v);
        __nv_bfloat16 l = __float2bfloat16(v - __bfloat162float(h));
        size_t o = (size_t)(n0 + ty + 8*i)*K + k0 + tx;
        Th[o] = h;
        Tl[o] = l;
    }
}

// ---------------- 8) HMMA bf16x3 GEMM: C = relu(A@B^T + bias) -> bf16 hi/lo ----------------
// A[M,K] hi/lo bf16 row-major, B[N,K] hi/lo bf16 row-major (= W^T).
// BM=64, BN=128, BK=32, 256 threads, warp grid 2x4, warp tile 32x32.
#define BM 64
#define BN 128
#define BK 32
#define SSTR 40                        // padded SMEM row stride (bf16 elems), 80B
#define AH0 0
#define AL0 (BM*SSTR)
#define BH0 (2*BM*SSTR)
#define BL0 (2*BM*SSTR + BN*SSTR)
#define BUFE (2*BM*SSTR + 2*BN*SSTR)   // elems per buffer = 15360
#define GEMM_SMEM (2*BUFE*2)           // bytes = 61440

__device__ __forceinline__ void gemm_load_chunk(u32 smbase, int buf,
    const __nv_bfloat16* __restrict__ Ah, const __nv_bfloat16* __restrict__ Al,
    const __nv_bfloat16* __restrict__ Bh, const __nv_bfloat16* __restrict__ Bl,
    int br, int bc, int K, int k0, int tid)
{
    u32 base = smbase + (u32)buf * (BUFE*2);
    int arow = tid >> 2;
    int cg   = (tid & 3) * 8;
    CPA16(base + (u32)(AH0 + arow*SSTR + cg)*2, Ah + (size_t)(br+arow)*K + k0 + cg);
    CPA16(base + (u32)(AL0 + arow*SSTR + cg)*2, Al + (size_t)(br+arow)*K + k0 + cg);
    #pragma unroll
    for (int i = 0; i < 2; i++) {
        int brow = (tid + i*256) >> 2;
        CPA16(base + (u32)(BH0 + brow*SSTR + cg)*2, Bh + (size_t)(bc+brow)*K + k0 + cg);
        CPA16(base + (u32)(BL0 + brow*SSTR + cg)*2, Bl + (size_t)(bc+brow)*K + k0 + cg);
    }
    CPA_COMMIT();
}

__global__ void __launch_bounds__(256) hgemm_kernel(
    const __nv_bfloat16* __restrict__ Ah, const __nv_bfloat16* __restrict__ Al,
    const __nv_bfloat16* __restrict__ Bh, const __nv_bfloat16* __restrict__ Bl,
    const float* __restrict__ bias,
    __nv_bfloat16* __restrict__ Chi, __nv_bfloat16* __restrict__ Clo,
    int K, int ldc, int do_relu)
{
    extern __shared__ __nv_bfloat16 sm[];
    u32 smbase = smem_u32(sm);
    int tid = threadIdx.x;
    int lane = tid & 31;
    int w = tid >> 5;
    int br = blockIdx.y * BM;
    int bc = blockIdx.x * BN;
    int wm = (w >> 2) * 32;        // 2 warps in M
    int wn = (w & 3) * 32;         // 4 warps in N

    float acc[2][4][4];
    #pragma unroll
    for (int mt = 0; mt < 2; mt++)
        #pragma unroll
        for (int nt = 0; nt < 4; nt++)
            #pragma unroll
            for (int e = 0; e < 4; e++) acc[mt][nt][e] = 0.0f;

    const int NC = K / BK;
    gemm_load_chunk(smbase, 0, Ah, Al, Bh, Bl, br, bc, K, 0, tid);

    for (int c = 0; c < NC; c++) {
        CPA_WAIT0();
        __syncthreads();
        if (c + 1 < NC)
            gemm_load_chunk(smbase, (c+1) & 1, Ah, Al, Bh, Bl, br, bc, K, (c+1)*BK, tid);

        u32 base = smbase + (u32)(c & 1) * (BUFE*2);
        #pragma unroll
        for (int ks = 0; ks < BK; ks += 16) {
            u32 afr[2][4], afl[2][4], bfr[4][2], bfl[4][2];
            #pragma unroll
            for (int mt = 0; mt < 2; mt++) {
                u32 ra = base + (u32)(AH0 + (wm + mt*16 + (lane & 15))*SSTR
                                       + ks + (lane >> 4)*8)*2;
                ldsm4(afr[mt], ra);
                ldsm4(afl[mt], ra + (u32)(AL0 - AH0)*2);
            }
            #pragma unroll
            for (int nt = 0; nt < 4; nt++) {
                u32 rb = base + (u32)(BH0 + (wn + nt*8 + (lane & 7))*SSTR
                                       + ks + ((lane >> 3) & 1)*8)*2;
                ldsm2(bfr[nt], rb);
                ldsm2(bfl[nt], rb + (u32)(BL0 - BH0)*2);
            }
            #pragma unroll
            for (int mt = 0; mt < 2; mt++)
                #pragma unroll
                for (int nt = 0; nt < 4; nt++) {
                    mma16816(acc[mt][nt], afr[mt], bfr[nt]);   // Ah*Bh
                    mma16816(acc[mt][nt], afr[mt], bfl[nt]);   // Ah*Bl
                    mma16816(acc[mt][nt], afl[mt], bfr[nt]);   // Al*Bh
                }
        }
        __syncthreads();
    }

    // epilogue: bias + relu + hi/lo split
    int g  = lane >> 2;
    int tg = lane & 3;
    #pragma unroll
    for (int mt = 0; mt < 2; mt++) {
        #pragma unroll
        for (int nt = 0; nt < 4; nt++) {
            int row0 = br + wm + mt*16 + g;
            int col0 = bc + wn + nt*8 + 2*tg;
            #pragma unroll
            for (int e = 0; e < 4; e++) {
                int row = row0 + (e >> 1)*8;
                int col = col0 + (e & 1);
                float v = acc[mt][nt][e] + bias[col];
                if (do_relu) v = fmaxf(v, 0.0f);
                __nv_bfloat16 h = __float2bfloat16(v);
                __nv_bfloat16 l = __float2bfloat16(v - __bfloat162float(h));
                Chi[(size_t)row*ldc + col] = h;
                Clo[(size_t)row*ldc + col] = l;
            }
        }
    }
}

// ---------------- 9) FC3 + unparameterize + keep gate ----------------
__global__ void fc3_final_kernel(const float* __restrict__ W3,
                                 const float* __restrict__ b3,
                                 float* __restrict__ out) {
    int mrow = blockIdx.x;
    int tid = threadIdx.x;     // 128
    float acc[4] = {0,0,0,0};
    for (int k = tid; k < HIDDEN; k += 128) {
        float hv = __bfloat162float(g_h2hi[mrow*HIDDEN + k]) +
                   __bfloat162float(g_h2lo[mrow*HIDDEN + k]);
        #pragma unroll
        for (int c = 0; c < 4; c++) acc[c] = fmaf(hv, W3[k*4 + c], acc[c]);
    }
    __shared__ float red[4][128];
    #pragma unroll
    for (int c = 0; c < 4; c++) red[c][tid] = acc[c];
    __syncthreads();
    for (int s = 64; s > 0; s >>= 1) {
        if (tid < s) {
            #pragma unroll
            for (int c = 0; c < 4; c++) red[c][tid] += red[c][tid + s];
        }
        __syncthreads();
    }
    if (tid == 0) {
        if (!g_keep[mrow]) {
            #pragma unroll
            for (int c = 0; c < 5; c++) out[mrow*5 + c] = 0.0f;
        } else {
            float d0 = red[0][0] + b3[0];
            float d1 = red[1][0] + b3[1];
            float d2 = red[2][0] + b3[2];
            float d3 = red[3][0] + b3[3];
            float sx = g_sel[mrow*4+0], sy = g_sel[mrow*4+1];
            float sw = g_sel[mrow*4+2], sh = g_sel[mrow*4+3];
            float acx = sx + sw * 0.5f;
            float acy = sy + sh * 0.5f;
            float cx = acx + d0 * sw;
            float cy = acy + d1 * sh;
            float w  = sw * expf(d2);
            float h  = sh * expf(d3);
            out[mrow*5+0] = cx - w * 0.5f;
            out[mrow*5+1] = cy - h * 0.5f;
            out[mrow*5+2] = w;
            out[mrow*5+3] = h;
            out[mrow*5+4] = g_scores[mrow];
        }
    }
}

// ---------------- launch ----------------
extern "C" void kernel_launch(void* const* d_in, const int* in_sizes, int n_in,
                              void* d_out, int out_size) {
    const float* features = (const float*)d_in[0];
    const float* rpn_obj  = (const float*)d_in[1];
    const float* rpn_reg  = (const float*)d_in[2];
    const float* W1 = (const float*)d_in[4];
    const float* b1 = (const float*)d_in[5];
    const float* W2 = (const float*)d_in[6];
    const float* b2 = (const float*)d_in[7];
    const float* W3 = (const float*)d_in[8];
    const float* b3 = (const float*)d_in[9];
    float* out = (float*)d_out;

    u64 *kA, *kB;
    __nv_bfloat16 *Ahi, *Alo, *W1Th, *W1Tl, *W2Th, *W2Tl, *h1hi, *h1lo, *h2hi, *h2lo;
    cudaGetSymbolAddress((void**)&kA, g_keysA);
    cudaGetSymbolAddress((void**)&kB, g_keysB);
    cudaGetSymbolAddress((void**)&Ahi, g_Ahi);
    cudaGetSymbolAddress((void**)&Alo, g_Alo);
    cudaGetSymbolAddress((void**)&W1Th, g_W1Th);
    cudaGetSymbolAddress((void**)&W1Tl, g_W1Tl);
    cudaGetSymbolAddress((void**)&W2Th, g_W2Th);
    cudaGetSymbolAddress((void**)&W2Tl, g_W2Tl);
    cudaGetSymbolAddress((void**)&h1hi, g_h1hi);
    cudaGetSymbolAddress((void**)&h1lo, g_h1lo);
    cudaGetSymbolAddress((void**)&h2hi, g_h2hi);
    cudaGetSymbolAddress((void**)&h2lo, g_h2lo);

    cudaFuncSetAttribute(hgemm_kernel,
                         cudaFuncAttributeMaxDynamicSharedMemorySize, GEMM_SMEM);

    // weight prep (independent of detection path)
    tsplit_kernel<<<dim3(HIDDEN/32, PDIM/32),   dim3(32,8)>>>(W1, W1Th, W1Tl, PDIM,   HIDDEN);
    tsplit_kernel<<<dim3(HIDDEN/32, HIDDEN/32), dim3(32,8)>>>(W2, W2Th, W2Tl, HIDDEN, HIDDEN);

    score_kernel<<<NA/256, 256>>>(rpn_obj, kA);
    sort1024_kernel<<<64, 1024>>>(kA, kB);
    merge_kernel<<<32, 1024>>>(kB, kA);
    merge_kernel<<<16, 1024>>>(kA, kB);
    merge_kernel<<<8,  1024>>>(kB, kA);
    merge_kernel<<<4,  1024>>>(kA, kB);
    merge_kernel<<<2,  1024>>>(kB, kA);
    merge_kernel<<<1,  1024>>>(kA, kB);

    gather_kernel<<<1, 512>>>(rpn_reg, kB);
    iou_kernel<<<512, 512>>>();
    nms_kernel<<<1, 256>>>();
    roi_kernel<<<512, 512>>>(features);

    dim3 gg(HIDDEN/BN, MAXDET/BM);   // 8 x 8 = 64 CTAs
    hgemm_kernel<<<gg, 256, GEMM_SMEM>>>(Ahi,  Alo,  W1Th, W1Tl, b1, h1hi, h1lo,
                                         PDIM,   HIDDEN, 1);
    hgemm_kernel<<<gg, 256, GEMM_SMEM>>>(h1hi, h1lo, W2Th, W2Tl, b2, h2hi, h2lo,
                                         HIDDEN, HIDDEN, 1);
    fc3_final_kernel<<<MAXDET, 128>>>(W3, b3, out);
}